// round 13
// baseline (speedup 1.0000x reference)
#include <cuda_runtime.h>
#include <cstdint>
#include <cstddef>

// Problem constants
#define NROW 8192
#define MCOL 32768
#define DIM  256
#define KTOP 10

// Work decomposition: item = (64 rows) x (4096 cols). 1024 items total,
// consumed by 296 persistent CTAs via an atomic counter.
#define MS    8
#define BR    64
#define BC    128
#define KC    16
#define NCH   (DIM / KC)          // 16
#define NTHR  128
#define CPS   (MCOL / MS)         // 4096 cols per split
#define TPS   (CPS / BC)          // 32 tiles per item
#define NITEM ((NROW / BR) * MS)  // 1024
#define GRID  296

#define NEGINF (__int_as_float(0xff800000))
#define IMAXI  0x7fffffff

// Scratch (device globals: legal, no runtime allocation)
__device__ float g_pv[MS * NROW * KTOP];
__device__ int   g_pi[MS * NROW * KTOP];
__device__ int   g_ctr;

typedef unsigned long long u64;

__device__ __forceinline__ u64 pk2(float lo, float hi) {
    u64 r; asm("mov.b64 %0, {%1, %2};" : "=l"(r) : "f"(lo), "f"(hi)); return r;
}
__device__ __forceinline__ void upk2(float& lo, float& hi, u64 p) {
    asm("mov.b64 {%0, %1}, %2;" : "=f"(lo), "=f"(hi) : "l"(p));
}
__device__ __forceinline__ void fma2(u64& d, u64 a, u64 b) {
    asm("fma.rn.f32x2 %0, %1, %2, %0;" : "+l"(d) : "l"(a), "l"(b));
}
// Strict total order: descending value, ties -> smaller index (jax stable top_k)
__device__ __forceinline__ bool better(float v, int i, float v2, int i2) {
    return (v > v2) || (v == v2 && i < i2);
}
// Local-memory sorted insert (dynamic indexing; rare path).
// Caller guarantees better(val,idx, tv[9],ti[9]).
__device__ __forceinline__ void insertL(float val, int idx, float* tv, int* ti) {
    int p = KTOP - 1;
    #pragma unroll 1
    while (p > 0 && better(val, idx, tv[p-1], ti[p-1])) {
        tv[p] = tv[p-1]; ti[p] = ti[p-1]; p--;
    }
    tv[p] = val; ti[p] = idx;
}
// Register sorted insert (constant indexing), for merge phases.
__device__ __forceinline__ void insert10(float val, int idx, float tv[KTOP], int ti[KTOP]) {
    bool b[KTOP];
    #pragma unroll
    for (int j = 0; j < KTOP; j++) b[j] = better(val, idx, tv[j], ti[j]);
    #pragma unroll
    for (int j = KTOP - 1; j >= 1; j--) {
        if (b[j]) { tv[j] = b[j-1] ? tv[j-1] : val; ti[j] = b[j-1] ? ti[j-1] : idx; }
    }
    if (b[0]) { tv[0] = val; ti[0] = idx; }
}

__global__ void reset_ctr_kernel() { g_ctr = 0; }

__global__ __launch_bounds__(NTHR, 2)
void gemm_topk_kernel(const float* __restrict__ Ag, const float* __restrict__ Bg) {
    // 24 KB pool: GEMM staging; reused as merge staging between items.
    __shared__ __align__(16) float pool[6144];
    float* As = pool;              // [2][KC][BR]: buf*1024 + kk*64 + r
    float* Bs = pool + 2048;       // [2][KC][BC]: buf*2048 + kk*128 + c
    float* mv = pool;              // merge overlay [16 rows][16 lists][10]
    int*   mi = (int*)(pool + 2560);
    __shared__ int sItem;

    const int tid = threadIdx.x;
    const int tx  = tid & 15;      // col group: 8 cols
    const int ty  = tid >> 4;      // row group: 8 rows (0..7)

    for (;;) {
        if (tid == 0) sItem = atomicAdd(&g_ctr, 1);
        __syncthreads();
        const int item = sItem;
        if (item >= NITEM) break;

        const int rowBase = (item >> 3) * BR;
        const int colBase = (item & 7) * CPS;
        const int split   = item & 7;

        // Per-row top-10: lists in local memory, 10th-value thresholds in regs.
        float tvL[8][KTOP]; int tiL[8][KTOP];
        float thr[8];
        #pragma unroll
        for (int r = 0; r < 8; r++) {
            #pragma unroll 1
            for (int j = 0; j < KTOP; j++) { tvL[r][j] = NEGINF; tiL[r][j] = IMAXI; }
            thr[r] = NEGINF;
        }

        u64 acc[8][4];
        float4 ra[2], rb[4];

        for (int t = 0; t < TPS; t++) {
            const int mbase = colBase + t * BC;

            #pragma unroll
            for (int r = 0; r < 8; r++)
                #pragma unroll
                for (int j = 0; j < 4; j++) acc[r][j] = 0ull;

            // ---- preload chunk 0 ----
            #pragma unroll
            for (int j = 0; j < 2; j++) {
                int lin = tid + NTHR * j;                 // 0..255
                ra[j] = *(const float4*)(Ag + (size_t)(rowBase + (lin & 63)) * DIM + 4 * (lin >> 6));
            }
            #pragma unroll
            for (int j = 0; j < 4; j++) {
                int lin = tid + NTHR * j;                 // 0..511
                rb[j] = *(const float4*)(Bg + (size_t)(mbase + (lin & 127)) * DIM + 4 * (lin >> 7));
            }
            #pragma unroll
            for (int j = 0; j < 2; j++) {
                int lin = tid + NTHR * j, rr = lin & 63, q = lin >> 6;
                As[(4*q+0)*64+rr]=ra[j].x; As[(4*q+1)*64+rr]=ra[j].y;
                As[(4*q+2)*64+rr]=ra[j].z; As[(4*q+3)*64+rr]=ra[j].w;
            }
            #pragma unroll
            for (int j = 0; j < 4; j++) {
                int lin = tid + NTHR * j, rr = lin & 127, q = lin >> 7;
                Bs[(4*q+0)*128+rr]=rb[j].x; Bs[(4*q+1)*128+rr]=rb[j].y;
                Bs[(4*q+2)*128+rr]=rb[j].z; Bs[(4*q+3)*128+rr]=rb[j].w;
            }
            __syncthreads();

            // ---- K loop: double-buffered chunks ----
            #pragma unroll 1
            for (int c = 0; c < NCH; c++) {
                const int buf = c & 1;
                if (c + 1 < NCH) {
                    const int k0 = (c + 1) * KC;
                    #pragma unroll
                    for (int j = 0; j < 2; j++) {
                        int lin = tid + NTHR * j;
                        ra[j] = *(const float4*)(Ag + (size_t)(rowBase + (lin & 63)) * DIM + k0 + 4 * (lin >> 6));
                    }
                    #pragma unroll
                    for (int j = 0; j < 4; j++) {
                        int lin = tid + NTHR * j;
                        rb[j] = *(const float4*)(Bg + (size_t)(mbase + (lin & 127)) * DIM + k0 + 4 * (lin >> 7));
                    }
                }
                const float* Ab = As + buf * 1024 + ty * 8;
                const float* Bb = Bs + buf * 2048 + tx * 8;
                #pragma unroll
                for (int kk = 0; kk < KC; kk++) {
                    float4 a0 = *(const float4*)(Ab + kk * 64);
                    float4 a1 = *(const float4*)(Ab + kk * 64 + 4);
                    float4 b0 = *(const float4*)(Bb + kk * 128);
                    float4 b1 = *(const float4*)(Bb + kk * 128 + 4);
                    u64 bp0 = pk2(b0.x, b0.y), bp1 = pk2(b0.z, b0.w);
                    u64 bp2 = pk2(b1.x, b1.y), bp3 = pk2(b1.z, b1.w);
                    float av[8] = {a0.x, a0.y, a0.z, a0.w, a1.x, a1.y, a1.z, a1.w};
                    #pragma unroll
                    for (int r = 0; r < 8; r++) {
                        u64 ap = pk2(av[r], av[r]);
                        fma2(acc[r][0], ap, bp0);
                        fma2(acc[r][1], ap, bp1);
                        fma2(acc[r][2], ap, bp2);
                        fma2(acc[r][3], ap, bp3);
                    }
                }
                __syncthreads();
                if (c + 1 < NCH) {
                    const int ob = buf ^ 1;
                    #pragma unroll
                    for (int j = 0; j < 2; j++) {
                        int lin = tid + NTHR * j, rr = lin & 63, q = lin >> 6;
                        As[ob*1024+(4*q+0)*64+rr]=ra[j].x; As[ob*1024+(4*q+1)*64+rr]=ra[j].y;
                        As[ob*1024+(4*q+2)*64+rr]=ra[j].z; As[ob*1024+(4*q+3)*64+rr]=ra[j].w;
                    }
                    #pragma unroll
                    for (int j = 0; j < 4; j++) {
                        int lin = tid + NTHR * j, rr = lin & 127, q = lin >> 7;
                        Bs[ob*2048+(4*q+0)*128+rr]=rb[j].x; Bs[ob*2048+(4*q+1)*128+rr]=rb[j].y;
                        Bs[ob*2048+(4*q+2)*128+rr]=rb[j].z; Bs[ob*2048+(4*q+3)*128+rr]=rb[j].w;
                    }
                    __syncthreads();
                }
            }

            // ---- selection: per-row gate on register threshold, rare local insert ----
            const int cbase = mbase + tx * 8;
            #pragma unroll
            for (int r = 0; r < 8; r++) {
                float v[8];
                upk2(v[0], v[1], acc[r][0]); upk2(v[2], v[3], acc[r][1]);
                upk2(v[4], v[5], acc[r][2]); upk2(v[6], v[7], acc[r][3]);
                float m01 = fmaxf(v[0], v[1]), m23 = fmaxf(v[2], v[3]);
                float m45 = fmaxf(v[4], v[5]), m67 = fmaxf(v[6], v[7]);
                float m = fmaxf(fmaxf(m01, m23), fmaxf(m45, m67));
                if (m > thr[r]) {
                    #pragma unroll
                    for (int cc = 0; cc < 8; cc++) {
                        if (v[cc] > thr[r]) {
                            const int idx = cbase + cc;
                            if (better(v[cc], idx, tvL[r][KTOP-1], tiL[r][KTOP-1]))
                                insertL(v[cc], idx, tvL[r], tiL[r]);
                        }
                    }
                    thr[r] = tvL[r][KTOP-1];
                }
            }
        }

        // ---- item epilogue: merge 16 lists per row, write split partials ----
        __syncthreads();   // staging -> merge overlay
        for (int b = 0; b < 4; b++) {               // 16 rows per batch
            if ((ty >> 1) == b) {
                const int rl = (ty & 1) * 8;
                #pragma unroll
                for (int r = 0; r < 8; r++)
                    #pragma unroll 1
                    for (int j = 0; j < KTOP; j++) {
                        mv[((rl + r) * 16 + tx) * KTOP + j] = tvL[r][j];
                        mi[((rl + r) * 16 + tx) * KTOP + j] = tiL[r][j];
                    }
            }
            __syncthreads();
            if (tid < 16) {
                float rv[KTOP]; int ri[KTOP];
                #pragma unroll
                for (int j = 0; j < KTOP; j++) { rv[j] = NEGINF; ri[j] = IMAXI; }
                for (int l = 0; l < 16; l++) {
                    #pragma unroll 1
                    for (int j = 0; j < KTOP; j++) {
                        float val = mv[(tid * 16 + l) * KTOP + j];
                        int   idx = mi[(tid * 16 + l) * KTOP + j];
                        if (!better(val, idx, rv[KTOP-1], ri[KTOP-1])) break;  // sorted list
                        insert10(val, idx, rv, ri);
                    }
                }
                const int row = rowBase + b * 16 + tid;
                const size_t base = ((size_t)split * NROW + row) * KTOP;
                #pragma unroll
                for (int j = 0; j < KTOP; j++) { g_pv[base + j] = rv[j]; g_pi[base + j] = ri[j]; }
            }
            __syncthreads();
        }
    }
}

// One thread per row: merge MS sorted 10-lists -> final indices as float32.
__global__ __launch_bounds__(256)
void final_merge_kernel(float* __restrict__ out) {
    const int row = blockIdx.x * blockDim.x + threadIdx.x;
    if (row >= NROW) return;
    float rv[KTOP]; int ri[KTOP];
    #pragma unroll
    for (int j = 0; j < KTOP; j++) { rv[j] = NEGINF; ri[j] = IMAXI; }
    for (int s = 0; s < MS; s++) {
        const size_t base = ((size_t)s * NROW + row) * KTOP;
        #pragma unroll 1
        for (int j = 0; j < KTOP; j++) {
            const float val = g_pv[base + j];
            const int   idx = g_pi[base + j];
            if (!better(val, idx, rv[KTOP-1], ri[KTOP-1])) break;  // sorted list
            insert10(val, idx, rv, ri);
        }
    }
    #pragma unroll
    for (int j = 0; j < KTOP; j++) out[row * KTOP + j] = (float)ri[j];
}

extern "C" void kernel_launch(void* const* d_in, const int* in_sizes, int n_in,
                              void* d_out, int out_size) {
    // Unit-agnostic input identification: text_embs largest, image_embs second.
    int iB = -1, iA = -1;
    for (int i = 0; i < n_in; i++) {
        if (iB < 0 || in_sizes[i] > in_sizes[iB]) { iA = iB; iB = i; }
        else if (iA < 0 || in_sizes[i] > in_sizes[iA]) { iA = i; }
    }
    const float* A = (const float*)d_in[(iA >= 0) ? iA : 0];  // image_embs [8192,256]
    const float* B = (const float*)d_in[(iB >= 0) ? iB : 1];  // text_embs  [32768,256]
    float* out = (float*)d_out;                               // [8192,10] float32 index values

    reset_ctr_kernel<<<1, 1>>>();
    gemm_topk_kernel<<<GRID, NTHR>>>(A, B);
    final_merge_kernel<<<NROW / 256, 256>>>(out);
}

// round 14
// speedup vs baseline: 1.7722x; 1.7722x over previous
#include <cuda_runtime.h>
#include <cstdint>
#include <cstddef>

// Problem constants
#define NROW 8192
#define MCOL 32768
#define DIM  256
#define KTOP 10

// Tiling: CTA = 64 rows x (M/2) cols, 8x8 micro-tile, 128 threads, occ 2.
#define MS    2
#define BR    64
#define BC    128
#define KC    16
#define NCH   (DIM / KC)          // 16
#define NTHR  128
#define CPS   (MCOL / MS)         // 16384 cols per split
#define TPS   (CPS / BC)          // 128 tiles per CTA
#define NRB   (NROW / BR)         // 128 row-blocks

#define NEGINF (__int_as_float(0xff800000))
#define IMAXI  0x7fffffff

// Device scratch (zero-init at load; g_done self-resets each call)
__device__ float g_pv[MS * NROW * KTOP];
__device__ int   g_pi[MS * NROW * KTOP];
__device__ int   g_done[NRB];

// Strict total order: descending value, ties -> smaller index (jax stable top_k)
__device__ __forceinline__ bool better(float v, int i, float v2, int i2) {
    return (v > v2) || (v == v2 && i < i2);
}
// Local-memory sorted insert (rare path). Caller guarantees it beats slot 9.
__device__ __forceinline__ void insertL(float val, int idx, float* tv, int* ti) {
    int p = KTOP - 1;
    #pragma unroll 1
    while (p > 0 && better(val, idx, tv[p-1], ti[p-1])) {
        tv[p] = tv[p-1]; ti[p] = ti[p-1]; p--;
    }
    tv[p] = val; ti[p] = idx;
}
// Register sorted insert (constant indexing), for merge phases.
__device__ __forceinline__ void insert10(float val, int idx, float tv[KTOP], int ti[KTOP]) {
    bool b[KTOP];
    #pragma unroll
    for (int j = 0; j < KTOP; j++) b[j] = better(val, idx, tv[j], ti[j]);
    #pragma unroll
    for (int j = KTOP - 1; j >= 1; j--) {
        if (b[j]) { tv[j] = b[j-1] ? tv[j-1] : val; ti[j] = b[j-1] ? ti[j-1] : idx; }
    }
    if (b[0]) { tv[0] = val; ti[0] = idx; }
}

__global__ __launch_bounds__(NTHR, 2)
void gemm_topk_kernel(const float* __restrict__ Ag, const float* __restrict__ Bg,
                      float* __restrict__ out) {
    // 24 KB pool: GEMM staging, reused as merge overlay in the epilogue.
    __shared__ __align__(16) float pool[6144];
    float* As = pool;              // [2][KC][BR]: buf*1024 + kk*64 + r
    float* Bs = pool + 2048;       // [2][KC][BC]: buf*2048 + kk*128 + c
    float* mv = pool;              // overlay [16 rows][16 lists][10]
    int*   mi = (int*)(pool + 2560);
    __shared__ int sLast;

    const int tid = threadIdx.x;
    const int tx  = tid & 15;      // col group: 8 cols
    const int ty  = tid >> 4;      // row group: 8 rows
    const int rb      = blockIdx.x >> 1;
    const int split   = blockIdx.x & 1;
    const int rowBase = rb * BR;
    const int colBase = split * CPS;

    // Per-row top-10: lists in local memory, 10th-value thresholds in regs.
    float tvL[8][KTOP]; int tiL[8][KTOP];
    float thr[8];
    #pragma unroll
    for (int r = 0; r < 8; r++) {
        #pragma unroll 1
        for (int j = 0; j < KTOP; j++) { tvL[r][j] = NEGINF; tiL[r][j] = IMAXI; }
        thr[r] = NEGINF;
    }

    float acc[8][8];
    float4 ra[2], rb4[4];

    for (int t = 0; t < TPS; t++) {
        const int mbase = colBase + t * BC;

        #pragma unroll
        for (int r = 0; r < 8; r++)
            #pragma unroll
            for (int cc = 0; cc < 8; cc++) acc[r][cc] = 0.0f;

        // ---- preload chunk 0 into buf 0 ----
        #pragma unroll
        for (int j = 0; j < 2; j++) {
            int lin = tid + NTHR * j;   // 0..255
            ra[j] = *(const float4*)(Ag + (size_t)(rowBase + (lin & 63)) * DIM + 4 * (lin >> 6));
        }
        #pragma unroll
        for (int j = 0; j < 4; j++) {
            int lin = tid + NTHR * j;   // 0..511
            rb4[j] = *(const float4*)(Bg + (size_t)(mbase + (lin & 127)) * DIM + 4 * (lin >> 7));
        }
        #pragma unroll
        for (int j = 0; j < 2; j++) {
            int lin = tid + NTHR * j, rr = lin & 63, q = lin >> 6;
            As[(4*q+0)*64+rr]=ra[j].x; As[(4*q+1)*64+rr]=ra[j].y;
            As[(4*q+2)*64+rr]=ra[j].z; As[(4*q+3)*64+rr]=ra[j].w;
        }
        #pragma unroll
        for (int j = 0; j < 4; j++) {
            int lin = tid + NTHR * j, rr = lin & 127, q = lin >> 7;
            Bs[(4*q+0)*128+rr]=rb4[j].x; Bs[(4*q+1)*128+rr]=rb4[j].y;
            Bs[(4*q+2)*128+rr]=rb4[j].z; Bs[(4*q+3)*128+rr]=rb4[j].w;
        }
        __syncthreads();

        // ---- K loop, double-buffered, ONE sync per chunk ----
        #pragma unroll 1
        for (int c = 0; c < NCH; c++) {
            const int buf = c & 1;
            const int ob  = buf ^ 1;
            if (c + 1 < NCH) {
                const int k0 = (c + 1) * KC;
                #pragma unroll
                for (int j = 0; j < 2; j++) {
                    int lin = tid + NTHR * j;
                    ra[j] = *(const float4*)(Ag + (size_t)(rowBase + (lin & 63)) * DIM + k0 + 4 * (lin >> 6));
                }
                #pragma unroll
                for (int j = 0; j < 4; j++) {
                    int lin = tid + NTHR * j;
                    rb4[j] = *(const float4*)(Bg + (size_t)(mbase + (lin & 127)) * DIM + k0 + 4 * (lin >> 7));
                }
            }
            const float* Ab = As + buf * 1024 + ty * 8;
            const float* Bb = Bs + buf * 2048 + tx * 8;
            #pragma unroll
            for (int kk = 0; kk < KC; kk++) {
                float4 a0 = *(const float4*)(Ab + kk * 64);
                float4 a1 = *(const float4*)(Ab + kk * 64 + 4);
                float4 b0 = *(const float4*)(Bb + kk * 128);
                float4 b1 = *(const float4*)(Bb + kk * 128 + 4);
                float av[8] = {a0.x, a0.y, a0.z, a0.w, a1.x, a1.y, a1.z, a1.w};
                float bv[8] = {b0.x, b0.y, b0.z, b0.w, b1.x, b1.y, b1.z, b1.w};
                #pragma unroll
                for (int r = 0; r < 8; r++)
                    #pragma unroll
                    for (int cc = 0; cc < 8; cc++)
                        acc[r][cc] = fmaf(av[r], bv[cc], acc[r][cc]);
            }
            if (c + 1 < NCH) {
                // store prefetched chunk into the buffer nobody reads this iter
                #pragma unroll
                for (int j = 0; j < 2; j++) {
                    int lin = tid + NTHR * j, rr = lin & 63, q = lin >> 6;
                    As[ob*1024+(4*q+0)*64+rr]=ra[j].x; As[ob*1024+(4*q+1)*64+rr]=ra[j].y;
                    As[ob*1024+(4*q+2)*64+rr]=ra[j].z; As[ob*1024+(4*q+3)*64+rr]=ra[j].w;
                }
                #pragma unroll
                for (int j = 0; j < 4; j++) {
                    int lin = tid + NTHR * j, rr = lin & 127, q = lin >> 7;
                    Bs[ob*2048+(4*q+0)*128+rr]=rb4[j].x; Bs[ob*2048+(4*q+1)*128+rr]=rb4[j].y;
                    Bs[ob*2048+(4*q+2)*128+rr]=rb4[j].z; Bs[ob*2048+(4*q+3)*128+rr]=rb4[j].w;
                }
            }
            __syncthreads();
        }

        // ---- selection: register-threshold gate, rare local insert ----
        const int cbase = mbase + tx * 8;
        #pragma unroll
        for (int r = 0; r < 8; r++) {
            float m01 = fmaxf(acc[r][0], acc[r][1]), m23 = fmaxf(acc[r][2], acc[r][3]);
            float m45 = fmaxf(acc[r][4], acc[r][5]), m67 = fmaxf(acc[r][6], acc[r][7]);
            float m = fmaxf(fmaxf(m01, m23), fmaxf(m45, m67));
            if (m > thr[r]) {
                #pragma unroll
                for (int cc = 0; cc < 8; cc++) {
                    if (acc[r][cc] > thr[r]) {
                        const int idx = cbase + cc;
                        if (better(acc[r][cc], idx, tvL[r][KTOP-1], tiL[r][KTOP-1]))
                            insertL(acc[r][cc], idx, tvL[r], tiL[r]);
                    }
                }
                thr[r] = tvL[r][KTOP-1];
            }
        }
    }

    // ---- epilogue A: in-CTA merge of 16 lists/row -> split partials ----
    __syncthreads();   // staging -> merge overlay
    for (int b = 0; b < 4; b++) {               // 16 rows per batch
        if ((ty >> 1) == b) {
            const int rl = (ty & 1) * 8;
            #pragma unroll
            for (int r = 0; r < 8; r++)
                #pragma unroll 1
                for (int j = 0; j < KTOP; j++) {
                    mv[((rl + r) * 16 + tx) * KTOP + j] = tvL[r][j];
                    mi[((rl + r) * 16 + tx) * KTOP + j] = tiL[r][j];
                }
        }
        __syncthreads();
        if (tid < 16) {
            float rv[KTOP]; int ri[KTOP];
            #pragma unroll
            for (int j = 0; j < KTOP; j++) { rv[j] = NEGINF; ri[j] = IMAXI; }
            for (int l = 0; l < 16; l++) {
                #pragma unroll 1
                for (int j = 0; j < KTOP; j++) {
                    float val = mv[(tid * 16 + l) * KTOP + j];
                    int   idx = mi[(tid * 16 + l) * KTOP + j];
                    if (!better(val, idx, rv[KTOP-1], ri[KTOP-1])) break;  // sorted list
                    insert10(val, idx, rv, ri);
                }
            }
            const int row = rowBase + b * 16 + tid;
            const size_t base = ((size_t)split * NROW + row) * KTOP;
            #pragma unroll
            for (int j = 0; j < KTOP; j++) { g_pv[base + j] = rv[j]; g_pi[base + j] = ri[j]; }
        }
        __syncthreads();
    }

    // ---- epilogue B: last CTA of this row-block merges both splits ----
    __threadfence();
    __syncthreads();
    if (tid == 0) {
        int old = atomicAdd(&g_done[rb], 1);
        int last = (old == 1);
        if (last) atomicExch(&g_done[rb], 0);   // self-reset for graph replays
        sLast = last;
    }
    __syncthreads();
    if (sLast && tid < BR) {
        __threadfence();                        // acquire partner's partials
        const int row = rowBase + tid;
        float av[KTOP], bv[KTOP]; int ai[KTOP], bi[KTOP];
        const size_t b0 = (size_t)row * KTOP;
        const size_t b1 = (size_t)NROW * KTOP + row * KTOP;
        #pragma unroll
        for (int j = 0; j < KTOP; j++) {
            av[j] = g_pv[b0 + j]; ai[j] = g_pi[b0 + j];
            bv[j] = g_pv[b1 + j]; bi[j] = g_pi[b1 + j];
        }
        int pa = 0, pb = 0;
        #pragma unroll
        for (int j = 0; j < KTOP; j++) {
            bool ta = better(av[pa], ai[pa], bv[pb], bi[pb]);
            int pick = ta ? ai[pa] : bi[pb];
            if (ta) pa++; else pb++;
            out[row * KTOP + j] = (float)pick;  // harness compares as float32
        }
    }
}

extern "C" void kernel_launch(void* const* d_in, const int* in_sizes, int n_in,
                              void* d_out, int out_size) {
    // Unit-agnostic input identification: text_embs largest, image_embs second.
    int iB = -1, iA = -1;
    for (int i = 0; i < n_in; i++) {
        if (iB < 0 || in_sizes[i] > in_sizes[iB]) { iA = iB; iB = i; }
        else if (iA < 0 || in_sizes[i] > in_sizes[iA]) { iA = i; }
    }
    const float* A = (const float*)d_in[(iA >= 0) ? iA : 0];  // image_embs [8192,256]
    const float* B = (const float*)d_in[(iB >= 0) ? iB : 1];  // text_embs  [32768,256]
    float* out = (float*)d_out;                               // [8192,10] float32 index values

    gemm_topk_kernel<<<NRB * MS, NTHR>>>(A, B, out);
}

// round 17
// speedup vs baseline: 2.3203x; 1.3093x over previous
#include <cuda_runtime.h>
#include <cstdint>
#include <cstddef>

// Problem constants
#define NROW 8192
#define MCOL 32768
#define DIM  256
#define KTOP 10

// Tiling: CTA = 64 rows x 8192 cols (1 of 4 col-splits), 4x8 micro-tile,
// 256 threads, occupancy 2 (two CTAs per SM hide LDS/barrier latency).
#define MS    4
#define BR    64
#define BC    128
#define KC    16
#define NCH   (DIM / KC)          // 16
#define NTHR  256
#define CPS   (MCOL / MS)         // 8192 cols per split
#define TPS   (CPS / BC)          // 64 tiles per CTA
#define NRB   (NROW / BR)         // 128 row-blocks
#define GRID  (NRB * MS)          // 512 CTAs

#define NEGINF (__int_as_float(0xff800000))
#define IMAXI  0x7fffffff

// Device scratch (zero-init at load; g_done self-resets every call)
__device__ float g_pv[MS * NROW * KTOP];
__device__ int   g_pi[MS * NROW * KTOP];
__device__ int   g_done[NRB];

// Strict total order: descending value, ties -> smaller index (jax stable top_k)
__device__ __forceinline__ bool better(float v, int i, float v2, int i2) {
    return (v > v2) || (v == v2 && i < i2);
}
// Local-memory sorted insert (rare path). Caller guarantees it beats slot 9.
__device__ __forceinline__ void insertL(float val, int idx, float* tv, int* ti) {
    int p = KTOP - 1;
    #pragma unroll 1
    while (p > 0 && better(val, idx, tv[p-1], ti[p-1])) {
        tv[p] = tv[p-1]; ti[p] = ti[p-1]; p--;
    }
    tv[p] = val; ti[p] = idx;
}
// Register sorted insert (constant indexing only), for merge phases.
__device__ __forceinline__ void insert10(float val, int idx, float tv[KTOP], int ti[KTOP]) {
    bool b[KTOP];
    #pragma unroll
    for (int j = 0; j < KTOP; j++) b[j] = better(val, idx, tv[j], ti[j]);
    #pragma unroll
    for (int j = KTOP - 1; j >= 1; j--) {
        if (b[j]) { tv[j] = b[j-1] ? tv[j-1] : val; ti[j] = b[j-1] ? ti[j-1] : idx; }
    }
    if (b[0]) { tv[0] = val; ti[0] = idx; }
}

__global__ __launch_bounds__(NTHR, 2)
void gemm_topk_kernel(const float* __restrict__ Ag, const float* __restrict__ Bg,
                      float* __restrict__ out) {
    // 24 KB pool: GEMM staging, reused as the merge overlay in the epilogue.
    __shared__ __align__(16) float pool[6144];
    float* As = pool;              // [2][KC][BR]: buf*1024 + kk*64 + r
    float* Bs = pool + 2048;       // [2][KC][BC]: buf*2048 + kk*128 + c
    float* mv = pool;              // overlay [16 rows][16 lists][10]
    int*   mi = (int*)(pool + 2560);
    __shared__ int sLast;

    const int tid = threadIdx.x;
    const int tx  = tid & 15;      // col group: cols {tx*4..+3, 64+tx*4..+3}
    const int ty  = tid >> 4;      // row group: 4 rows (conflict-free LDS)
    const int rb      = blockIdx.x >> 2;
    const int split   = blockIdx.x & 3;
    const int rowBase = rb * BR;
    const int colBase = split * CPS;

    // Per-row top-10: lists in local memory, 10th-value thresholds in regs.
    float tvL[4][KTOP]; int tiL[4][KTOP];
    float thr[4];
    #pragma unroll
    for (int r = 0; r < 4; r++) {
        #pragma unroll 1
        for (int j = 0; j < KTOP; j++) { tvL[r][j] = NEGINF; tiL[r][j] = IMAXI; }
        thr[r] = NEGINF;
    }

    float acc[4][8];
    float4 ra, rb0, rb1;

    for (int t = 0; t < TPS; t++) {
        const int mbase = colBase + t * BC;

        #pragma unroll
        for (int r = 0; r < 4; r++)
            #pragma unroll
            for (int cc = 0; cc < 8; cc++) acc[r][cc] = 0.0f;

        // ---- preload chunk 0 into buf 0 (LDG -> regs -> STS k-major) ----
        {
            int rr = tid & 63, q = tid >> 6;               // A: 256 float4
            ra = *(const float4*)(Ag + (size_t)(rowBase + rr) * DIM + 4 * q);
            As[(4*q+0)*64+rr]=ra.x; As[(4*q+1)*64+rr]=ra.y;
            As[(4*q+2)*64+rr]=ra.z; As[(4*q+3)*64+rr]=ra.w;
        }
        {
            int l0 = tid, l1 = tid + NTHR;                 // B: 512 float4
            int r0 = l0 & 127, q0 = l0 >> 7, r1 = l1 & 127, q1 = l1 >> 7;
            rb0 = *(const float4*)(Bg + (size_t)(mbase + r0) * DIM + 4 * q0);
            rb1 = *(const float4*)(Bg + (size_t)(mbase + r1) * DIM + 4 * q1);
            Bs[(4*q0+0)*128+r0]=rb0.x; Bs[(4*q0+1)*128+r0]=rb0.y;
            Bs[(4*q0+2)*128+r0]=rb0.z; Bs[(4*q0+3)*128+r0]=rb0.w;
            Bs[(4*q1+0)*128+r1]=rb1.x; Bs[(4*q1+1)*128+r1]=rb1.y;
            Bs[(4*q1+2)*128+r1]=rb1.z; Bs[(4*q1+3)*128+r1]=rb1.w;
        }
        __syncthreads();

        // ---- K loop: double-buffered, ONE sync per chunk ----
        #pragma unroll 1
        for (int c = 0; c < NCH; c++) {
            const int buf = c & 1;
            const int ob  = buf ^ 1;
            if (c + 1 < NCH) {
                const int k0 = (c + 1) * KC;
                int rr = tid & 63, q = tid >> 6;
                ra = *(const float4*)(Ag + (size_t)(rowBase + rr) * DIM + k0 + 4 * q);
                int l0 = tid, l1 = tid + NTHR;
                int r0 = l0 & 127, q0 = l0 >> 7, r1 = l1 & 127, q1 = l1 >> 7;
                rb0 = *(const float4*)(Bg + (size_t)(mbase + r0) * DIM + k0 + 4 * q0);
                rb1 = *(const float4*)(Bg + (size_t)(mbase + r1) * DIM + k0 + 4 * q1);
            }
            const float* Ab = As + buf * 1024 + ty * 4;
            const float* Bb = Bs + buf * 2048 + tx * 4;    // conflict-free: 16B stride
            #pragma unroll
            for (int kk = 0; kk < KC; kk++) {
                float4 a4 = *(const float4*)(Ab + kk * 128 / 2);      // kk*64
                float4 b0 = *(const float4*)(Bb + kk * 128);          // cols tx*4..+3
                float4 b1 = *(const float4*)(Bb + kk * 128 + 64);     // cols 64+tx*4..+3
                float av[4] = {a4.x, a4.y, a4.z, a4.w};
                float bv[8] = {b0.x, b0.y, b0.z, b0.w, b1.x, b1.y, b1.z, b1.w};
                #pragma unroll
                for (int r = 0; r < 4; r++)
                    #pragma unroll
                    for (int cc = 0; cc < 8; cc++)
                        acc[r][cc] = fmaf(av[r], bv[cc], acc[r][cc]);
            }
            if (c + 1 < NCH) {
                // store prefetched chunk into the buffer nobody reads this iter
                int rr = tid & 63, q = tid >> 6;
                As[ob*1024+(4*q+0)*64+rr]=ra.x; As[ob*1024+(4*q+1)*64+rr]=ra.y;
                As[ob*1024+(4*q+2)*64+rr]=ra.z; As[ob*1024+(4*q+3)*64+rr]=ra.w;
                int l0 = tid, l1 = tid + NTHR;
                int r0 = l0 & 127, q0 = l0 >> 7, r1 = l1 & 127, q1 = l1 >> 7;
                Bs[ob*2048+(4*q0+0)*128+r0]=rb0.x; Bs[ob*2048+(4*q0+1)*128+r0]=rb0.y;
                Bs[ob*2048+(4*q0+2)*128+r0]=rb0.z; Bs[ob*2048+(4*q0+3)*128+r0]=rb0.w;
                Bs[ob*2048+(4*q1+0)*128+r1]=rb1.x; Bs[ob*2048+(4*q1+1)*128+r1]=rb1.y;
                Bs[ob*2048+(4*q1+2)*128+r1]=rb1.z; Bs[ob*2048+(4*q1+3)*128+r1]=rb1.w;
            }
            __syncthreads();
        }

        // ---- selection: register-threshold gate, rare local-mem insert ----
        #pragma unroll
        for (int r = 0; r < 4; r++) {
            float m01 = fmaxf(acc[r][0], acc[r][1]), m23 = fmaxf(acc[r][2], acc[r][3]);
            float m45 = fmaxf(acc[r][4], acc[r][5]), m67 = fmaxf(acc[r][6], acc[r][7]);
            float m = fmaxf(fmaxf(m01, m23), fmaxf(m45, m67));
            if (m > thr[r]) {
                #pragma unroll
                for (int cc = 0; cc < 8; cc++) {
                    if (acc[r][cc] > thr[r]) {
                        const int idx = mbase + ((cc < 4) ? (tx*4 + cc) : (64 + tx*4 + cc - 4));
                        if (better(acc[r][cc], idx, tvL[r][KTOP-1], tiL[r][KTOP-1]))
                            insertL(acc[r][cc], idx, tvL[r], tiL[r]);
                    }
                }
                thr[r] = tvL[r][KTOP-1];
            }
        }
    }

    // ---- epilogue A: in-CTA merge of 16 lists per row -> split partials ----
    __syncthreads();   // staging -> merge overlay
    for (int b = 0; b < 4; b++) {               // 16 rows per batch
        if ((ty >> 2) == b) {
            const int rl = (ty & 3) * 4;
            #pragma unroll
            for (int r = 0; r < 4; r++)
                #pragma unroll 1
                for (int j = 0; j < KTOP; j++) {
                    mv[((rl + r) * 16 + tx) * KTOP + j] = tvL[r][j];
                    mi[((rl + r) * 16 + tx) * KTOP + j] = tiL[r][j];
                }
        }
        __syncthreads();
        if (tid < 16) {
            float rv[KTOP]; int ri[KTOP];
            #pragma unroll
            for (int j = 0; j < KTOP; j++) { rv[j] = NEGINF; ri[j] = IMAXI; }
            for (int l = 0; l < 16; l++) {
                #pragma unroll 1
                for (int j = 0; j < KTOP; j++) {
                    float val = mv[(tid * 16 + l) * KTOP + j];
                    int   idx = mi[(tid * 16 + l) * KTOP + j];
                    if (!better(val, idx, rv[KTOP-1], ri[KTOP-1])) break;  // sorted list
                    insert10(val, idx, rv, ri);
                }
            }
            const int row = rowBase + b * 16 + tid;
            const size_t base = ((size_t)split * NROW + row) * KTOP;
            #pragma unroll
            for (int j = 0; j < KTOP; j++) { g_pv[base + j] = rv[j]; g_pi[base + j] = ri[j]; }
        }
        __syncthreads();
    }

    // ---- epilogue B: last CTA of this row-block merges all MS splits ----
    __threadfence();
    __syncthreads();
    if (tid == 0) {
        int old = atomicAdd(&g_done[rb], 1);
        int last = (old == MS - 1);
        if (last) atomicExch(&g_done[rb], 0);   // self-reset for graph replays
        sLast = last;
    }
    __syncthreads();
    if (sLast && tid < BR) {
        __threadfence();                        // acquire other splits' partials
        const int row = rowBase + tid;
        float rv[KTOP]; int ri[KTOP];
        #pragma unroll
        for (int j = 0; j < KTOP; j++) { rv[j] = NEGINF; ri[j] = IMAXI; }
        for (int s = 0; s < MS; s++) {
            const size_t base = ((size_t)s * NROW + row) * KTOP;
            #pragma unroll 1
            for (int j = 0; j < KTOP; j++) {
                const float val = g_pv[base + j];
                const int   idx = g_pi[base + j];
                if (!better(val, idx, rv[KTOP-1], ri[KTOP-1])) break;  // sorted list
                insert10(val, idx, rv, ri);
            }
        }
        #pragma unroll
        for (int j = 0; j < KTOP; j++)
            out[row * KTOP + j] = (float)ri[j];  // harness compares as float32
    }
}

extern "C" void kernel_launch(void* const* d_in, const int* in_sizes, int n_in,
                              void* d_out, int out_size) {
    // Unit-agnostic input identification: text_embs largest, image_embs second.
    int iB = -1, iA = -1;
    for (int i = 0; i < n_in; i++) {
        if (iB < 0 || in_sizes[i] > in_sizes[iB]) { iA = iB; iB = i; }
        else if (iA < 0 || in_sizes[i] > in_sizes[iA]) { iA = i; }
    }
    const float* A = (const float*)d_in[(iA >= 0) ? iA : 0];  // image_embs [8192,256]
    const float* B = (const float*)d_in[(iB >= 0) ? iB : 1];  // text_embs  [32768,256]
    float* out = (float*)d_out;                               // [8192,10] float32 index values

    gemm_topk_kernel<<<GRID, NTHR>>>(A, B, out);
}